// round 1
// baseline (speedup 1.0000x reference)
#include <cuda_runtime.h>
#include <math.h>

#define G_ 256
#define M_ 256
#define N_ 65536
#define E_ 1048576
#define C_ 3
#define K_ 5
#define D_ 128

// Scratch (static device globals; no runtime allocation).
__device__ float g_u0[C_][N_];   // Mdj[g, s[g], :] per class
__device__ float g_mk[C_][N_];   // Mdj[g, :, t[g]] per class
__device__ float g_u1[C_][N_];   // u0 @ Mdj per class
__device__ float g_a0[N_];       // Adj[g, s[g], :]
__device__ float g_ak[N_];       // Adj[g, :, t[g]]
__device__ float g_a1[N_];       // a0 @ Adj
__device__ float g_ukn[C_][G_];  // Mdj[g,s,t]
__device__ float g_ast[G_];      // Adj[g,s,t]
__device__ float g_scal[9];      // info[0..2], l2[3..5], path[6..8]

__global__ void k_zero() {
    int i  = blockIdx.x * blockDim.x + threadIdx.x;
    int st = gridDim.x * blockDim.x;
    float* p1 = &g_u0[0][0];
    float* p2 = &g_mk[0][0];
    float* p3 = &g_u1[0][0];
    for (int j = i; j < C_ * N_; j += st) { p1[j] = 0.f; p2[j] = 0.f; p3[j] = 0.f; }
    for (int j = i; j < N_; j += st) { g_a0[j] = 0.f; g_ak[j] = 0.f; g_a1[j] = 0.f; }
    if (i < C_ * G_) (&g_ukn[0][0])[i] = 0.f;
    if (i < G_) g_ast[i] = 0.f;
    if (i < 9) g_scal[i] = 0.f;
}

// Attention embedding: H_out[c,g,:] = softmax(hg[g] @ H[c]^T) @ H[c]
__global__ void k_att(const float* __restrict__ hg, const float* __restrict__ H,
                      float* __restrict__ out) {
    int b = blockIdx.x;         // c*G + g
    int c = b / G_, g = b % G_;
    int d = threadIdx.x;        // 128 threads = D
    const float* Hc = H + c * K_ * D_;
    float h = hg[g * D_ + d];

    __shared__ float sc[K_];
    __shared__ float red[4];
    int lane = threadIdx.x & 31, w = threadIdx.x >> 5;
    #pragma unroll
    for (int k = 0; k < K_; k++) {
        float x = h * Hc[k * D_ + d];
        #pragma unroll
        for (int o = 16; o > 0; o >>= 1) x += __shfl_down_sync(0xffffffffu, x, o);
        if (lane == 0) red[w] = x;
        __syncthreads();
        if (threadIdx.x == 0) sc[k] = red[0] + red[1] + red[2] + red[3];
        __syncthreads();
    }
    float mx = sc[0];
    #pragma unroll
    for (int k = 1; k < K_; k++) mx = fmaxf(mx, sc[k]);
    float ex[K_], se = 0.f;
    #pragma unroll
    for (int k = 0; k < K_; k++) { ex[k] = __expf(sc[k] - mx); se += ex[k]; }
    float inv = 1.f / se;
    float o = 0.f;
    #pragma unroll
    for (int k = 0; k < K_; k++) o += ex[k] * inv * Hc[k * D_ + d];
    out[(c * G_ + g) * D_ + d] = o;
}

// Edge pass 1: info/l2 reductions + gated scatters for u0/mk/a0/ak/uk_num/adj_st.
__global__ void k_edge1(const int* __restrict__ ei, const float* __restrict__ sij,
                        const int* __restrict__ s, const int* __restrict__ t) {
    __shared__ int ss[G_], tt[G_];
    for (int j = threadIdx.x; j < G_; j += blockDim.x) { ss[j] = s[j]; tt[j] = t[j]; }
    __syncthreads();
    const int* src = ei;
    const int* dst = ei + E_;
    float acc[6] = {0.f, 0.f, 0.f, 0.f, 0.f, 0.f};
    int st = gridDim.x * blockDim.x;
    for (int e = blockIdx.x * blockDim.x + threadIdx.x; e < E_; e += st) {
        int sv = src[e], dv = dst[e];
        int g = sv >> 8, r = sv & 255, c = dv & 255;
        float v[3];
        v[0] = sij[e]; v[1] = sij[E_ + e]; v[2] = sij[2 * E_ + e];
        #pragma unroll
        for (int k = 0; k < 3; k++) {
            float x = v[k];
            acc[k]     += x * __logf(2.f * x + 1e-6f)
                        + (1.f - x) * __logf((1.f - x) * (1.f / 0.500001f) + 1e-6f);
            acc[3 + k] += x * x;
        }
        bool hr = (r == ss[g]);
        bool hc = (c == tt[g]);
        if (hr) {
            int idx = (g << 8) | c;
            atomicAdd(&g_u0[0][idx], v[0]);
            atomicAdd(&g_u0[1][idx], v[1]);
            atomicAdd(&g_u0[2][idx], v[2]);
            atomicAdd(&g_a0[idx], 1.f);
            if (hc) {
                atomicAdd(&g_ukn[0][g], v[0]);
                atomicAdd(&g_ukn[1][g], v[1]);
                atomicAdd(&g_ukn[2][g], v[2]);
                atomicAdd(&g_ast[g], 1.f);
            }
        }
        if (hc) {
            int idx = (g << 8) | r;
            atomicAdd(&g_mk[0][idx], v[0]);
            atomicAdd(&g_mk[1][idx], v[1]);
            atomicAdd(&g_mk[2][idx], v[2]);
            atomicAdd(&g_ak[idx], 1.f);
        }
    }
    // block-reduce the 6 accumulators, one atomic per value per block
    __shared__ float red[6][8];
    int lane = threadIdx.x & 31, w = threadIdx.x >> 5;
    #pragma unroll
    for (int k = 0; k < 6; k++) {
        float x = acc[k];
        #pragma unroll
        for (int o = 16; o > 0; o >>= 1) x += __shfl_down_sync(0xffffffffu, x, o);
        if (lane == 0) red[k][w] = x;
    }
    __syncthreads();
    if (threadIdx.x < 6) {
        float x = 0.f;
        #pragma unroll
        for (int j = 0; j < 8; j++) x += red[threadIdx.x][j];
        atomicAdd(&g_scal[threadIdx.x], x);
    }
}

// Edge pass 2: u1[g,c] += u0[g,r]*v ; a1[g,c] += a0[g,r]. Skip when a0==0
// (a0[g,r]==0  <=>  u0[k][g,r]==0 for all k, since both gated on r==s[g]).
__global__ void k_edge2(const int* __restrict__ ei, const float* __restrict__ sij) {
    const int* src = ei;
    const int* dst = ei + E_;
    int st = gridDim.x * blockDim.x;
    for (int e = blockIdx.x * blockDim.x + threadIdx.x; e < E_; e += st) {
        int sv = src[e], dv = dst[e];
        int g = sv >> 8;
        int ri = (g << 8) | (sv & 255);
        float a0 = g_a0[ri];
        if (a0 != 0.f) {
            int ci = (g << 8) | (dv & 255);
            atomicAdd(&g_a1[ci], a0);
            float u00 = g_u0[0][ri], u01 = g_u0[1][ri], u02 = g_u0[2][ri];
            atomicAdd(&g_u1[0][ci], u00 * sij[e]);
            atomicAdd(&g_u1[1][ci], u01 * sij[E_ + e]);
            atomicAdd(&g_u1[2][ci], u02 * sij[2 * E_ + e]);
        }
    }
}

// Per-group path loss finalization. One block per group, 256 threads (= M).
__global__ void k_path(const float* __restrict__ pw) {
    int g = blockIdx.x;
    int m = threadIdx.x;
    int idx = (g << 8) | m;
    float ak = g_ak[idx];
    float a0 = g_a0[idx], a1 = g_a1[idx];
    float d0 = a0 * ak; d0 = (d0 == 0.f) ? 1e-8f : d0;
    float d1 = a1 * ak; d1 = (d1 == 0.f) ? 1e-8f : d1;
    float loc[6];
    #pragma unroll
    for (int k = 0; k < 3; k++) {
        float mkv = g_mk[k][idx];
        loc[k]     = g_u0[k][idx] * mkv / d0;
        loc[3 + k] = g_u1[k][idx] * mkv / d1;
    }
    __shared__ float red[6][8];
    int lane = threadIdx.x & 31, w = threadIdx.x >> 5;
    #pragma unroll
    for (int k = 0; k < 6; k++) {
        float x = loc[k];
        #pragma unroll
        for (int o = 16; o > 0; o >>= 1) x = fmaxf(x, __shfl_down_sync(0xffffffffu, x, o));
        if (lane == 0) red[k][w] = x;
    }
    __syncthreads();
    if (threadIdx.x == 0) {
        float w1 = fminf(fmaxf(pw[1], 1e-10f), 1.f);
        float w2 = fminf(fmaxf(pw[2], 1e-10f), 1.f);
        float ast = g_ast[g]; ast = (ast == 0.f) ? 1e-8f : ast;
        #pragma unroll
        for (int k = 0; k < 3; k++) {
            float mx0 = red[k][0], mx1 = red[3 + k][0];
            #pragma unroll
            for (int j = 1; j < 8; j++) {
                mx0 = fmaxf(mx0, red[k][j]);
                mx1 = fmaxf(mx1, red[3 + k][j]);
            }
            float uk = g_ukn[k][g] / ast;
            uk += w1 * (mx0 + 1e-8f);            // l=0: power 1/1
            uk += w2 * sqrtf(mx1 + 1e-8f);       // l=1: power 1/2
            uk *= (1.f / 3.f);                   // / MAXLEN
            atomicAdd(&g_scal[6 + k], -logf(uk + 1e-8f));
        }
    }
}

__global__ void k_final(float* __restrict__ out) {
    if (threadIdx.x == 0) {
        float info = (g_scal[0] + g_scal[1] + g_scal[2]) * (1.f / (3.f * (float)E_));
        float l2   = (g_scal[3] + g_scal[4] + g_scal[5]) * (1.f / (3.f * 2.f * (float)G_));
        float path = (g_scal[6] + g_scal[7] + g_scal[8]) * (1.f / (3.f * (float)G_));
        out[C_ * G_ * D_ + 0] = info;
        out[C_ * G_ * D_ + 1] = path;
        out[C_ * G_ * D_ + 2] = l2;
    }
}

extern "C" void kernel_launch(void* const* d_in, const int* in_sizes, int n_in,
                              void* d_out, int out_size) {
    const float* hg  = (const float*)d_in[0];
    const float* H   = (const float*)d_in[1];
    const float* pw  = (const float*)d_in[2];
    const float* sij = (const float*)d_in[3];
    const int*   ei  = (const int*)d_in[4];
    // d_in[5] = batch (derivable as node/M, unused)
    const int*   s   = (const int*)d_in[6];
    const int*   t   = (const int*)d_in[7];
    float* out = (float*)d_out;

    k_zero<<<1024, 256>>>();
    k_att<<<C_ * G_, 128>>>(hg, H, out);
    k_edge1<<<1024, 256>>>(ei, sij, s, t);
    k_edge2<<<1024, 256>>>(ei, sij);
    k_path<<<G_, 256>>>(pw);
    k_final<<<1, 32>>>(out);
}